// round 15
// baseline (speedup 1.0000x reference)
#include <cuda_runtime.h>
#include <cuda_fp16.h>
#include <cuda_bf16.h>

// HashEncoder: 4-level dense-grid trilinear interpolation, F=4.
// R15 = R14 + depth-2 software pipeline on the gather: slot k+1's position
// (prefetched at k-1) is converted to frac/gbase at iteration k and its
// record gather ISSUED at k, consumed at k+1. Reg cap (256,6) <=42 regs,
// 48 warps/SM. fp16 cell records (64B/cell, pre-scaled by 2^12); per
// (cell,feature): 4 half2 groups g(dy*2+dx) = {c(dx,dy,z0), c(dx,dy,z1)}.
// Encode: 2 points per warp-slot (lane = q*16 + L*4 + f); ONE 16B gather per
// lane per slot -> 4 L1tex wavefronts/point (gather optimum). Positions
// __ldcs, output __stcs.
//
// Level meta: res={32,43,56,74}, offsets={0,32768,112280,287896}, total=693120.

#define NPARAMS 693120
#define VAL_SCALE 4096.0f
#define INV_VAL_SCALE (1.0f / 4096.0f)

__device__ __half g_cells_h[NPARAMS * 32];   // 44.4 MB scratch (64B/cell)

__constant__ int c_res[4] = {32, 43, 56, 74};
__constant__ int c_off[4] = {0, 32768, 112280, 287896};

// ---------------------------------------------------------------- preprocess table
// thread t = gbase*2 + fp : builds records for features {2fp, 2fp+1}.
__global__ void __launch_bounds__(256)
build_cells(const float* __restrict__ tab)
{
    int t = blockIdx.x * blockDim.x + threadIdx.x;
    if (t >= NPARAMS * 2) return;

    int gbase = t >> 1;
    int fp = t & 1;

    int L = (gbase >= 32768) + (gbase >= 112280) + (gbase >= 287896);
    int res  = c_res[L];
    int off  = c_off[L];
    int res2 = res * res;
    int local = gbase - off;

    int z   = local / res2;          // padding cells may exceed grid; clamp below
    int rem = local - z * res2;
    int y   = rem / res;
    int x   = rem - y * res;

    float2 v[4][2];                  // [g=dy*2+dx][dz] = (feat 2fp, feat 2fp+1)
#pragma unroll
    for (int g = 0; g < 4; ++g) {
        int xi = min(x + (g & 1), res - 1);
        int yi = min(y + (g >> 1), res - 1);
#pragma unroll
        for (int dz = 0; dz < 2; ++dz) {
            int zi = min(z + dz, res - 1);
            int idx = off + xi + yi * res + zi * res2;
            float2 w = __ldg((const float2*)&tab[idx * 4 + 2 * fp]);
            v[g][dz] = make_float2(w.x * VAL_SCALE, w.y * VAL_SCALE);
        }
    }

    uint4 r0, r1;
    {
        half2 h0 = __floats2half2_rn(v[0][0].x, v[0][1].x);
        half2 h1 = __floats2half2_rn(v[1][0].x, v[1][1].x);
        half2 h2 = __floats2half2_rn(v[2][0].x, v[2][1].x);
        half2 h3 = __floats2half2_rn(v[3][0].x, v[3][1].x);
        r0.x = *(unsigned*)&h0; r0.y = *(unsigned*)&h1;
        r0.z = *(unsigned*)&h2; r0.w = *(unsigned*)&h3;
    }
    {
        half2 h0 = __floats2half2_rn(v[0][0].y, v[0][1].y);
        half2 h1 = __floats2half2_rn(v[1][0].y, v[1][1].y);
        half2 h2 = __floats2half2_rn(v[2][0].y, v[2][1].y);
        half2 h3 = __floats2half2_rn(v[3][0].y, v[3][1].y);
        r1.x = *(unsigned*)&h0; r1.y = *(unsigned*)&h1;
        r1.z = *(unsigned*)&h2; r1.w = *(unsigned*)&h3;
    }

    uint4* dst = (uint4*)g_cells_h;
    dst[gbase * 4 + 2 * fp]     = r0;
    dst[gbase * 4 + 2 * fp + 1] = r1;
}

// ---------------------------------------------------------------- main pass
__device__ __forceinline__ void
frac_gbase(float x, float y, float z, float s, int res, int res2, int off,
           float& fx, float& fy, float& fz, int& gbase)
{
    float px = fmaf(x, s, 0.5f);
    float py = fmaf(y, s, 0.5f);
    float pz = fmaf(z, s, 0.5f);
    int ix = __float2int_rd(px);     // px,py,pz >= 0.5: rd == floor
    int iy = __float2int_rd(py);
    int iz = __float2int_rd(pz);
    fx = px - __int2float_rn(ix);
    fy = py - __int2float_rn(iy);
    fz = pz - __int2float_rn(iz);
    gbase = off + ix + iy * res + iz * res2;
}

__device__ __forceinline__ float
lerp_rec(uint4 rec, float fx, float fy, float fz)
{
    half2 g0 = *(half2*)&rec.x;      // (dx,dy)=(0,0), {z0,z1}
    half2 g1 = *(half2*)&rec.y;      // (1,0)
    half2 g2 = *(half2*)&rec.z;      // (0,1)
    half2 g3 = *(half2*)&rec.w;      // (1,1)
    half2 fx2 = __float2half2_rn(fx);
    half2 fy2 = __float2half2_rn(fy);
    half2 a = __hfma2(fx2, __hsub2(g1, g0), g0);
    half2 b = __hfma2(fx2, __hsub2(g3, g2), g2);
    half2 c = __hfma2(fy2, __hsub2(b, a), a);    // {z0, z1}
    float clo = __low2float(c);
    float chi = __high2float(c);
    return fmaf(fz, chi - clo, clo) * INV_VAL_SCALE;
}

// Fast path: depth-2 pipeline (pos at k-1, gather issued at k, math at k+1).
__device__ __forceinline__ void
encode_fast(const float* __restrict__ pos, float* __restrict__ out,
            const __half* __restrict__ cells_f, float s,
            int res, int res2, int off,
            int p0, int q, int lane)
{
    const float* pp = pos + 3 * (p0 + q);      // this lane's first point

    // Prologue: slot 0 position -> frac/gbase -> issue rec0; prefetch pos1.
    float fX, fY, fZ; int gb;
    {
        float x = __ldcs(&pp[0]);
        float y = __ldcs(&pp[1]);
        float z = __ldcs(&pp[2]);
        frac_gbase(x, y, z, s, res, res2, off, fX, fY, fZ, gb);
    }
    uint4 rec = __ldg((const uint4*)(cells_f + (size_t)gb * 32));
    float nx = __ldcs(&pp[6]);
    float ny = __ldcs(&pp[7]);
    float nz = __ldcs(&pp[8]);

#pragma unroll
    for (int k = 0; k < 8; ++k) {
        // Issue next slot's gather (independent of current math).
        float nfX = 0.f, nfY = 0.f, nfZ = 0.f;
        uint4 nrec = rec;
        if (k < 7) {
            int ngb;
            frac_gbase(nx, ny, nz, s, res, res2, off, nfX, nfY, nfZ, ngb);
            nrec = __ldg((const uint4*)(cells_f + (size_t)ngb * 32));
        }
        // Prefetch the position after next.
        if (k < 6) {
            nx = __ldcs(&pp[6 * (k + 2) + 0]);
            ny = __ldcs(&pp[6 * (k + 2) + 1]);
            nz = __ldcs(&pp[6 * (k + 2) + 2]);
        }

        // Consume current record.
        float r = lerp_rec(rec, fX, fY, fZ);
        __stcs(&out[(size_t)p0 * 16 + 32 * k + lane], r);

        fX = nfX; fY = nfY; fZ = nfZ; rec = nrec;
    }
}

// Guard path (tail warp only; never taken when n % 16 == 0).
__device__ __forceinline__ void
encode_guard(const float* __restrict__ pos, float* __restrict__ out,
             const __half* __restrict__ cells_f, float s,
             int res, int res2, int off,
             int p0, int q, int lane, int n)
{
    for (int k = 0; k < 8; ++k) {
        int p = p0 + 2 * k + q;
        bool valid = (p < n);
        int pc = valid ? p : (n - 1);

        float x = __ldcs(&pos[3 * pc + 0]);
        float y = __ldcs(&pos[3 * pc + 1]);
        float z = __ldcs(&pos[3 * pc + 2]);

        float fx, fy, fz; int gb;
        frac_gbase(x, y, z, s, res, res2, off, fx, fy, fz, gb);
        uint4 rec = __ldg((const uint4*)(cells_f + (size_t)gb * 32));
        float r = lerp_rec(rec, fx, fy, fz);

        if (valid)
            __stcs(&out[(size_t)p0 * 16 + 32 * k + lane], r);
    }
}

__global__ void __launch_bounds__(256, 6)   // caps regs at 42: 48 warps/SM
encode_kernel(const float* __restrict__ pos, float* __restrict__ out,
              float4 scales, int n)
{
    const int lane = threadIdx.x & 31;
    const int warp = (blockIdx.x * blockDim.x + threadIdx.x) >> 5;
    const int p0 = warp * 16;
    if (p0 >= n) return;

    const int q = lane >> 4;            // point parity within slot
    const int L = (lane >> 2) & 3;      // level
    const int f = lane & 3;             // feature

    const float s = (L < 2) ? (L == 0 ? scales.x : scales.y)
                            : (L == 2 ? scales.z : scales.w);
    const int res  = c_res[L];
    const int res2 = res * res;
    const int off  = c_off[L];
    const __half* cells_f = g_cells_h + f * 8;

    if (p0 + 16 <= n)
        encode_fast(pos, out, cells_f, s, res, res2, off, p0, q, lane);
    else
        encode_guard(pos, out, cells_f, s, res, res2, off, p0, q, lane, n);
}

// ---------------------------------------------------------------- launcher
extern "C" void kernel_launch(void* const* d_in, const int* in_sizes, int n_in,
                              void* d_out, int out_size)
{
    const float* positions = (const float*)d_in[0];
    const float* table = (const float*)d_in[1];
    float* out = (float*)d_out;

    int n = in_sizes[0] / 3;

    // Level scales: double math, rounded to fp32 like JAX's weak promotion.
    double b = 1.3195079565048218;
    double p = 1.0;
    float s[4];
    for (int l = 0; l < 4; ++l) {
        s[l] = (float)(32.0 * p - 1.0);
        p *= b;
    }
    float4 scales = make_float4(s[0], s[1], s[2], s[3]);

    int bb = (NPARAMS * 2 + 255) / 256;
    build_cells<<<bb, 256>>>(table);

    int warps = (n + 15) / 16;
    int blocks = (warps * 32 + 255) / 256;
    encode_kernel<<<blocks, 256>>>(positions, out, scales, n);
}